// round 13
// baseline (speedup 1.0000x reference)
#include <cuda_runtime.h>
#include <cuda_fp16.h>
#include <stdint.h>
#include <math.h>

#define MB_N    100000
#define MB_PAD  100096          // 782 * 128
#define E_DIM   1536
#define NPIX    784
#define NPAD    896             // 7 m-tiles of 128
#define OUTHW   224
#define OUTPIX  (224*224)

// ---- mma GEMM tiling (R6 schedule, fp16 data + fp16 accumulate) ----
#define BK      64
#define NKS     (E_DIM / BK)    // 24
#define STG     3
#define ROWB    144             // bytes per smem row (128B data + 16B pad)
#define TILE_B  (128 * ROWB)    // 18432
#define STAGE_B (2 * TILE_B)    // 36864
#define SMEM_REQ (STG * STAGE_B)  // 110592

// ---------------- device scratch ----------------
__device__ float         g_emb[NPIX * E_DIM];
__device__ __half        g_emb_h[NPAD * E_DIM];             // pad rows stay zero
__device__ __half        g_bank_h[(size_t)MB_PAD * E_DIM];  // pad rows stay zero
__device__ float         g_row_norm[NPAD];                  // pad rows zero
__device__ float         g_bank_norm[MB_PAD];               // pad rows = 1e30
__device__ unsigned int  g_min[NPAD];
__device__ float         g_d2row[MB_N];
__device__ int           g_argmax;
__device__ float         g_amap28[NPIX];
__device__ float         g_t0[OUTPIX];
__device__ float         g_t1[OUTPIX];

// ---------------- helpers ----------------
__device__ __forceinline__ void cpasync16(uint32_t dst, const void* src) {
    asm volatile("cp.async.cg.shared.global [%0], [%1], 16;" :: "r"(dst), "l"(src));
}

__device__ __forceinline__ void ldsm4(uint32_t (&r)[4], uint32_t addr) {
    asm volatile("ldmatrix.sync.aligned.m8n8.x4.shared.b16 {%0,%1,%2,%3}, [%4];"
                 : "=r"(r[0]), "=r"(r[1]), "=r"(r[2]), "=r"(r[3]) : "r"(addr));
}

// fp16 accumulate HMMA: D(f16x2 x2) += A(f16) * B(f16)
__device__ __forceinline__ void mma16816h(uint32_t (&d)[2], const uint32_t (&a)[4],
                                          uint32_t b0, uint32_t b1) {
    asm volatile(
        "mma.sync.aligned.m16n8k16.row.col.f16.f16.f16.f16 "
        "{%0,%1}, {%2,%3,%4,%5}, {%6,%7}, {%0,%1};"
        : "+r"(d[0]), "+r"(d[1])
        : "r"(a[0]), "r"(a[1]), "r"(a[2]), "r"(a[3]), "r"(b0), "r"(b1));
}

// ---------------- 1) embedding + row norms + fp16 copy ----------------
__global__ void __launch_bounds__(256) embed_kernel(const float* __restrict__ f2,
                                                    const float* __restrict__ f3) {
    __shared__ float red[256];
    int p = blockIdx.x;
    int y = p / 28, x = p % 28;
    int tid = threadIdx.x;
    float ss = 0.f;

    for (int c = tid; c < 512; c += 256) {
        const float* base = f2 + c * 784;
        float s = 0.f;
        #pragma unroll
        for (int dy = -1; dy <= 1; dy++) {
            int yy = y + dy;
            if (yy < 0 || yy >= 28) continue;
            #pragma unroll
            for (int dx = -1; dx <= 1; dx++) {
                int xx = x + dx;
                if (xx < 0 || xx >= 28) continue;
                s += base[yy * 28 + xx];
            }
        }
        float v = s * (1.f / 9.f);
        g_emb[p * E_DIM + c] = v;
        g_emb_h[(size_t)p * E_DIM + c] = __float2half_rn(v);
        ss += v * v;
    }
    int y2 = y >> 1, x2 = x >> 1;
    for (int c = tid; c < 1024; c += 256) {
        const float* base = f3 + c * 196;
        float s = 0.f;
        #pragma unroll
        for (int dy = -1; dy <= 1; dy++) {
            int yy = y2 + dy;
            if (yy < 0 || yy >= 14) continue;
            #pragma unroll
            for (int dx = -1; dx <= 1; dx++) {
                int xx = x2 + dx;
                if (xx < 0 || xx >= 14) continue;
                s += base[yy * 14 + xx];
            }
        }
        float v = s * (1.f / 9.f);
        g_emb[p * E_DIM + 512 + c] = v;
        g_emb_h[(size_t)p * E_DIM + 512 + c] = __float2half_rn(v);
        ss += v * v;
    }
    red[tid] = ss;
    __syncthreads();
    for (int off = 128; off > 0; off >>= 1) {
        if (tid < off) red[tid] += red[tid + off];
        __syncthreads();
    }
    if (tid == 0) {
        g_row_norm[p] = red[0];
        g_min[p] = 0x7f800000u;
    }
}

// ---------------- 2) bank fp32 -> fp16 + norms (pad norm = 1e30) ----------------
__global__ void __launch_bounds__(256) convert_bank_kernel(const float* __restrict__ bank) {
    int tid = threadIdx.x;
    if (blockIdx.x == 0 && tid < (NPAD - NPIX)) g_min[NPIX + tid] = 0x7f800000u;
    int wid  = (blockIdx.x * 256 + tid) >> 5;
    int lane = tid & 31;
    int nw = (gridDim.x * 256) >> 5;
    for (int r = wid; r < MB_PAD; r += nw) {
        if (r < MB_N) {
            const float* row = bank + (size_t)r * E_DIM;
            __half* orow = g_bank_h + (size_t)r * E_DIM;
            float s = 0.f;
            for (int k = lane * 8; k < E_DIM; k += 256) {
                float4 a = *(const float4*)(row + k);
                float4 b = *(const float4*)(row + k + 4);
                s += a.x*a.x + a.y*a.y + a.z*a.z + a.w*a.w;
                s += b.x*b.x + b.y*b.y + b.z*b.z + b.w*b.w;
                __half2 h0 = __floats2half2_rn(a.x, a.y);
                __half2 h1 = __floats2half2_rn(a.z, a.w);
                __half2 h2 = __floats2half2_rn(b.x, b.y);
                __half2 h3 = __floats2half2_rn(b.z, b.w);
                uint4 o;
                o.x = *(unsigned int*)&h0;
                o.y = *(unsigned int*)&h1;
                o.z = *(unsigned int*)&h2;
                o.w = *(unsigned int*)&h3;
                *(uint4*)(orow + k) = o;
            }
            #pragma unroll
            for (int off = 16; off > 0; off >>= 1)
                s += __shfl_xor_sync(0xffffffffu, s, off);
            if (lane == 0) g_bank_norm[r] = s;
        } else {
            if (lane == 0) g_bank_norm[r] = 1e30f;
        }
    }
}

// ---------------- 3) fp16 mma.sync (f16 accumulate) distance GEMM + fused min ----
__global__ void __launch_bounds__(256, 2) distmin_mma_kernel() {
    extern __shared__ char smem[];
    uint32_t smem_u32;
    asm("{ .reg .u64 t; cvta.to.shared.u64 t, %1; cvt.u32.u64 %0, t; }"
        : "=r"(smem_u32) : "l"(smem));

    const int tid  = threadIdx.x;
    const int wid  = tid >> 5;
    const int lane = tid & 31;
    const int m0 = blockIdx.x * 128;
    const int n0 = blockIdx.y * 128;
    const int wm = wid >> 2;          // 0..1 -> 64-row half
    const int wn = wid & 3;           // 0..3 -> 32-col quarter
    const int m_base = wm * 64;
    const int n_base = wn * 32;

    uint32_t hacc[4][4][2];           // packed half2 accumulators
    #pragma unroll
    for (int i = 0; i < 4; i++)
        #pragma unroll
        for (int j = 0; j < 4; j++) {
            hacc[i][j][0] = 0u;
            hacc[i][j][1] = 0u;
        }

    const int g   = lane >> 3;
    const int lr  = lane & 7;
    const int a_row = lr + (g & 1) * 8;
    const int a_kb  = (g >> 1) * 16;
    const int b_row = lr + (g >> 1) * 8;
    const int b_kb  = (g & 1) * 16;

    auto issue = [&](int it) {
        uint32_t sb = smem_u32 + (uint32_t)(it % STG) * STAGE_B;
        int kk = it * BK;
        const __half* abase = g_emb_h + (size_t)m0 * E_DIM + kk;
        #pragma unroll
        for (int i = 0; i < 4; i++) {
            int f = tid + i * 256;
            int r = f >> 3, c = f & 7;
            cpasync16(sb + r * ROWB + c * 16, abase + (size_t)r * E_DIM + c * 8);
        }
        const __half* bbase = g_bank_h + (size_t)n0 * E_DIM + kk;
        #pragma unroll
        for (int i = 0; i < 4; i++) {
            int f = tid + i * 256;
            int r = f >> 3, c = f & 7;
            cpasync16(sb + TILE_B + r * ROWB + c * 16, bbase + (size_t)r * E_DIM + c * 8);
        }
        asm volatile("cp.async.commit_group;" ::: "memory");
    };

    issue(0);
    issue(1);

    for (int it = 0; it < NKS; it++) {
        if (it < NKS - 1) asm volatile("cp.async.wait_group 1;" ::: "memory");
        else              asm volatile("cp.async.wait_group 0;" ::: "memory");
        __syncthreads();
        if (it + 2 < NKS) issue(it + 2);

        uint32_t sa = smem_u32 + (uint32_t)(it % STG) * STAGE_B;
        uint32_t sbb = sa + TILE_B;
        #pragma unroll
        for (int ks = 0; ks < 4; ks++) {
            uint32_t a[4][4];
            #pragma unroll
            for (int mi = 0; mi < 4; mi++)
                ldsm4(a[mi], sa + (uint32_t)(m_base + mi * 16 + a_row) * ROWB + ks * 32 + a_kb);
            uint32_t b[2][4];
            #pragma unroll
            for (int p = 0; p < 2; p++)
                ldsm4(b[p], sbb + (uint32_t)(n_base + p * 16 + b_row) * ROWB + ks * 32 + b_kb);
            #pragma unroll
            for (int mi = 0; mi < 4; mi++) {
                #pragma unroll
                for (int ni = 0; ni < 4; ni++)
                    mma16816h(hacc[mi][ni], a[mi], b[ni >> 1][(ni & 1) * 2],
                              b[ni >> 1][(ni & 1) * 2 + 1]);
            }
        }
    }

    // ---- epilogue: unpack half2 -> fp32, d2 = rn + bn - 2*dot, min, atomicMin ----
    const int qid = lane >> 2;
    const int qtd = lane & 3;
    float bnv[4][2];
    #pragma unroll
    for (int ni = 0; ni < 4; ni++) {
        int n = n0 + n_base + ni * 8 + qtd * 2;
        bnv[ni][0] = g_bank_norm[n];
        bnv[ni][1] = g_bank_norm[n + 1];
    }
    #pragma unroll
    for (int mi = 0; mi < 4; mi++) {
        int r0 = m0 + m_base + mi * 16 + qid;
        int r1 = r0 + 8;
        float rn0 = g_row_norm[r0];
        float rn1 = g_row_norm[r1];
        float min0 = 1e30f, min1 = 1e30f;
        #pragma unroll
        for (int ni = 0; ni < 4; ni++) {
            float2 lo = __half22float2(*(__half2*)&hacc[mi][ni][0]);   // row qid
            float2 hi = __half22float2(*(__half2*)&hacc[mi][ni][1]);   // row qid+8
            min0 = fminf(min0, fmaxf(rn0 + bnv[ni][0] - 2.f * lo.x, 0.f));
            min0 = fminf(min0, fmaxf(rn0 + bnv[ni][1] - 2.f * lo.y, 0.f));
            min1 = fminf(min1, fmaxf(rn1 + bnv[ni][0] - 2.f * hi.x, 0.f));
            min1 = fminf(min1, fmaxf(rn1 + bnv[ni][1] - 2.f * hi.y, 0.f));
        }
        min0 = fminf(min0, __shfl_xor_sync(0xffffffffu, min0, 1));
        min0 = fminf(min0, __shfl_xor_sync(0xffffffffu, min0, 2));
        min1 = fminf(min1, __shfl_xor_sync(0xffffffffu, min1, 1));
        min1 = fminf(min1, __shfl_xor_sync(0xffffffffu, min1, 2));
        if (qtd == 0) {
            atomicMin(&g_min[r0], __float_as_uint(min0));
            atomicMin(&g_min[r1], __float_as_uint(min1));
        }
    }
}

// ---------------- 4) sqrt scores + argmax ----------------
__global__ void __launch_bounds__(1024) scores_kernel() {
    __shared__ float sv[1024];
    __shared__ int   si[1024];
    int tid = threadIdx.x;
    float s = -1e30f;
    if (tid < NPIX) {
        float d2 = __uint_as_float(g_min[tid]);
        s = sqrtf(fmaxf(d2, 1e-12f));
        g_amap28[tid] = s;
    }
    sv[tid] = s;
    si[tid] = tid;
    __syncthreads();
    for (int off = 512; off > 0; off >>= 1) {
        if (tid < off) {
            if (sv[tid + off] > sv[tid]) { sv[tid] = sv[tid + off]; si[tid] = si[tid + off]; }
        }
        __syncthreads();
    }
    if (tid == 0) g_argmax = si[0];
}

// ---------------- 5) argmax-row distances (fp32 emb x fp16 bank, fp32 accumulate) ----
__global__ void __launch_bounds__(256) row_dist_kernel() {
    __shared__ float e[E_DIM];
    int tid = threadIdx.x;
    int rstar = g_argmax;
    for (int i = tid; i < E_DIM; i += 256)
        e[i] = g_emb[(size_t)rstar * E_DIM + i];
    __syncthreads();
    float rn = g_row_norm[rstar];
    int wid  = (blockIdx.x * 256 + tid) >> 5;
    int lane = tid & 31;
    int nw = (gridDim.x * 256) >> 5;
    for (int r = wid; r < MB_N; r += nw) {
        const __half* row = g_bank_h + (size_t)r * E_DIM;
        uint4 u[6];
        #pragma unroll
        for (int j = 0; j < 6; j++)
            u[j] = *(const uint4*)(row + lane * 8 + j * 256);
        float s = 0.f;
        #pragma unroll
        for (int j = 0; j < 6; j++) {
            int k = lane * 8 + j * 256;
            float2 f0 = __half22float2(*(__half2*)&u[j].x);
            float2 f1 = __half22float2(*(__half2*)&u[j].y);
            float2 f2 = __half22float2(*(__half2*)&u[j].z);
            float2 f3 = __half22float2(*(__half2*)&u[j].w);
            s += f0.x * e[k]     + f0.y * e[k + 1] + f1.x * e[k + 2] + f1.y * e[k + 3];
            s += f2.x * e[k + 4] + f2.y * e[k + 5] + f3.x * e[k + 6] + f3.y * e[k + 7];
        }
        #pragma unroll
        for (int off = 16; off > 0; off >>= 1)
            s += __shfl_xor_sync(0xffffffffu, s, off);
        if (lane == 0)
            g_d2row[r] = fmaxf(rn + g_bank_norm[r] - 2.f * s, 0.f);
    }
}

// ---------------- 6) top-9 + anomaly score ----------------
__global__ void __launch_bounds__(1024) top9_kernel(float* __restrict__ out, int out_size) {
    __shared__ float s[1024 * 9];
    __shared__ float rv[1024];
    __shared__ int   ri[1024];
    __shared__ float cf[9];
    int tid = threadIdx.x;

    float t[9];
    #pragma unroll
    for (int i = 0; i < 9; i++) t[i] = __int_as_float(0x7f800000);
    for (int j = tid; j < MB_N; j += 1024) {
        float v = g_d2row[j];
        if (v < t[8]) {
            t[8] = v;
            #pragma unroll
            for (int i = 8; i > 0; i--) {
                float a = fminf(t[i - 1], t[i]);
                float b = fmaxf(t[i - 1], t[i]);
                t[i - 1] = a; t[i] = b;
            }
        }
    }
    #pragma unroll
    for (int i = 0; i < 9; i++) s[tid * 9 + i] = t[i];
    __syncthreads();

    for (int r = 0; r < 9; r++) {
        float lv = __int_as_float(0x7f800000);
        int   li = -1;
        #pragma unroll
        for (int i = 0; i < 9; i++) {
            float v = s[tid * 9 + i];
            if (v < lv) { lv = v; li = tid * 9 + i; }
        }
        rv[tid] = lv; ri[tid] = li;
        __syncthreads();
        for (int off = 512; off > 0; off >>= 1) {
            if (tid < off) {
                if (rv[tid + off] < rv[tid]) { rv[tid] = rv[tid + off]; ri[tid] = ri[tid + off]; }
            }
            __syncthreads();
        }
        if (tid == 0) {
            cf[r] = sqrtf(fmaxf(rv[0], 1e-12f));
            s[ri[0]] = __int_as_float(0x7f800000);
        }
        __syncthreads();
    }

    if (tid == 0) {
        double emax = exp((double)cf[8]);
        double sum = 0.0;
        #pragma unroll
        for (int i = 0; i < 9; i++) sum += exp((double)cf[i]);
        double weight = 1.0 - emax / sum;
        out[out_size - 1] = (float)(weight * (double)cf[0]);
    }
}

// ---------------- 7) bilinear resize 28 -> 224 ----------------
__global__ void __launch_bounds__(256) resize_kernel() {
    int o = blockIdx.x * 256 + threadIdx.x;
    if (o >= OUTPIX) return;
    int oy = o / OUTHW, ox = o % OUTHW;
    float fy = oy * 0.125f - 0.4375f;
    float fx = ox * 0.125f - 0.4375f;
    int y0 = (int)floorf(fy);
    int x0 = (int)floorf(fx);
    float wy = fy - (float)y0;
    float wx = fx - (float)x0;
    int y0c = min(max(y0, 0), 27), y1c = min(max(y0 + 1, 0), 27);
    int x0c = min(max(x0, 0), 27), x1c = min(max(x0 + 1, 0), 27);
    float v00 = g_amap28[y0c * 28 + x0c];
    float v01 = g_amap28[y0c * 28 + x1c];
    float v10 = g_amap28[y1c * 28 + x0c];
    float v11 = g_amap28[y1c * 28 + x1c];
    g_t0[o] = (1.f - wy) * ((1.f - wx) * v00 + wx * v01)
            + wy * ((1.f - wx) * v10 + wx * v11);
}

// ---------------- 8/9) separable gaussian ----------------
__device__ __forceinline__ int refl224(int i) {
    if (i < 0) return -1 - i;
    if (i > 223) return 447 - i;
    return i;
}

__global__ void __launch_bounds__(256) gaussv_kernel() {
    __shared__ float w[33];
    int tid = threadIdx.x;
    if (tid < 33) {
        float d = (float)tid - 16.f;
        w[tid] = expf(-d * d / 32.f);
    }
    __syncthreads();
    float Z = 0.f;
    #pragma unroll
    for (int i = 0; i < 33; i++) Z += w[i];
    float inv = 1.f / Z;
    int o = blockIdx.x * 256 + tid;
    if (o >= OUTPIX) return;
    int y = o / OUTHW, x = o % OUTHW;
    float s = 0.f;
    #pragma unroll
    for (int d = 0; d < 33; d++) {
        int yy = refl224(y + d - 16);
        s += w[d] * g_t0[yy * OUTHW + x];
    }
    g_t1[o] = s * inv;
}

__global__ void __launch_bounds__(256) gaussh_kernel(float* __restrict__ out) {
    __shared__ float w[33];
    int tid = threadIdx.x;
    if (tid < 33) {
        float d = (float)tid - 16.f;
        w[tid] = expf(-d * d / 32.f);
    }
    __syncthreads();
    float Z = 0.f;
    #pragma unroll
    for (int i = 0; i < 33; i++) Z += w[i];
    float inv = 1.f / Z;
    int o = blockIdx.x * 256 + tid;
    if (o >= OUTPIX) return;
    int y = o / OUTHW, x = o % OUTHW;
    float s = 0.f;
    #pragma unroll
    for (int d = 0; d < 33; d++) {
        int xx = refl224(x + d - 16);
        s += w[d] * g_t1[y * OUTHW + xx];
    }
    out[o] = s * inv;
}

// ---------------- launch ----------------
extern "C" void kernel_launch(void* const* d_in, const int* in_sizes, int n_in,
                              void* d_out, int out_size) {
    const float* f2   = (const float*)d_in[0];
    const float* f3   = (const float*)d_in[1];
    const float* bank = (const float*)d_in[2];
    float* out = (float*)d_out;

    cudaFuncSetAttribute(distmin_mma_kernel,
                         cudaFuncAttributeMaxDynamicSharedMemorySize, SMEM_REQ);

    embed_kernel<<<NPIX, 256>>>(f2, f3);
    convert_bank_kernel<<<1184, 256>>>(bank);

    dim3 g(NPAD / 128, MB_PAD / 128);   // (7, 782): x fastest -> B-tile reuse in L2
    distmin_mma_kernel<<<g, 256, SMEM_REQ>>>();

    scores_kernel<<<1, 1024>>>();
    row_dist_kernel<<<1563, 256>>>();
    top9_kernel<<<1, 1024>>>(out, out_size);

    resize_kernel<<<(OUTPIX + 255) / 256, 256>>>();
    gaussv_kernel<<<(OUTPIX + 255) / 256, 256>>>();
    gaussh_kernel<<<(OUTPIX + 255) / 256, 256>>>(out);
}

// round 15
// speedup vs baseline: 1.0666x; 1.0666x over previous
#include <cuda_runtime.h>
#include <cuda_fp16.h>
#include <stdint.h>
#include <math.h>

#define MB_N    100000
#define MB_PAD  100096          // 782 * 128
#define E_DIM   1536
#define NPIX    784
#define NPAD    896
#define OUTHW   224
#define OUTPIX  (224*224)

// ---- mma GEMM tiling (R6 schedule, fp16 data + fp16 accumulate) ----
#define BK      64
#define NKS     (E_DIM / BK)    // 24
#define STG     3
#define ROWB    144             // bytes per smem row (128B data + 16B pad)
#define TILE_B  (128 * ROWB)    // 18432
#define STAGE_B (2 * TILE_B)    // 36864
#define SMEM_REQ (STG * STAGE_B)  // 110592

// ---------------- device scratch ----------------
__device__ float         g_emb[NPIX * E_DIM];
__device__ __half        g_emb_h[NPAD * E_DIM];             // pad rows stay zero
__device__ __half        g_bank_h[(size_t)MB_PAD * E_DIM];  // pad rows stay zero
__device__ float         g_row_norm[NPAD];
__device__ float         g_bank_norm[MB_PAD];               // pad rows = 1e30
__device__ unsigned int  g_min[NPAD];
__device__ float         g_d2row[MB_N];
__device__ int           g_argmax;
__device__ float         g_amap28[NPIX];
__device__ float         g_t0[OUTPIX];
__device__ float         g_t1[OUTPIX];

// ---------------- helpers ----------------
__device__ __forceinline__ void cpasync16(uint32_t dst, const void* src) {
    asm volatile("cp.async.cg.shared.global [%0], [%1], 16;" :: "r"(dst), "l"(src));
}

__device__ __forceinline__ void ldsm4(uint32_t (&r)[4], uint32_t addr) {
    asm volatile("ldmatrix.sync.aligned.m8n8.x4.shared.b16 {%0,%1,%2,%3}, [%4];"
                 : "=r"(r[0]), "=r"(r[1]), "=r"(r[2]), "=r"(r[3]) : "r"(addr));
}

__device__ __forceinline__ void mma16816h(uint32_t (&d)[2], const uint32_t (&a)[4],
                                          uint32_t b0, uint32_t b1) {
    asm volatile(
        "mma.sync.aligned.m16n8k16.row.col.f16.f16.f16.f16 "
        "{%0,%1}, {%2,%3,%4,%5}, {%6,%7}, {%0,%1};"
        : "+r"(d[0]), "+r"(d[1])
        : "r"(a[0]), "r"(a[1]), "r"(a[2]), "r"(a[3]), "r"(b0), "r"(b1));
}

// ---------------- 1) embedding + row norms + fp16 copy ----------------
__global__ void __launch_bounds__(256) embed_kernel(const float* __restrict__ f2,
                                                    const float* __restrict__ f3) {
    __shared__ float red[256];
    int p = blockIdx.x;
    int y = p / 28, x = p % 28;
    int tid = threadIdx.x;
    float ss = 0.f;

    for (int c = tid; c < 512; c += 256) {
        const float* base = f2 + c * 784;
        float s = 0.f;
        #pragma unroll
        for (int dy = -1; dy <= 1; dy++) {
            int yy = y + dy;
            if (yy < 0 || yy >= 28) continue;
            #pragma unroll
            for (int dx = -1; dx <= 1; dx++) {
                int xx = x + dx;
                if (xx < 0 || xx >= 28) continue;
                s += base[yy * 28 + xx];
            }
        }
        float v = s * (1.f / 9.f);
        g_emb[p * E_DIM + c] = v;
        g_emb_h[(size_t)p * E_DIM + c] = __float2half_rn(v);
        ss += v * v;
    }
    int y2 = y >> 1, x2 = x >> 1;
    for (int c = tid; c < 1024; c += 256) {
        const float* base = f3 + c * 196;
        float s = 0.f;
        #pragma unroll
        for (int dy = -1; dy <= 1; dy++) {
            int yy = y2 + dy;
            if (yy < 0 || yy >= 14) continue;
            #pragma unroll
            for (int dx = -1; dx <= 1; dx++) {
                int xx = x2 + dx;
                if (xx < 0 || xx >= 14) continue;
                s += base[yy * 14 + xx];
            }
        }
        float v = s * (1.f / 9.f);
        g_emb[p * E_DIM + 512 + c] = v;
        g_emb_h[(size_t)p * E_DIM + 512 + c] = __float2half_rn(v);
        ss += v * v;
    }
    red[tid] = ss;
    __syncthreads();
    for (int off = 128; off > 0; off >>= 1) {
        if (tid < off) red[tid] += red[tid + off];
        __syncthreads();
    }
    if (tid == 0) {
        g_row_norm[p] = red[0];
        g_min[p] = 0x7f800000u;
    }
}

// ---------------- 2) bank fp32 -> fp16 + norms (pad norm = 1e30) ----------------
__global__ void __launch_bounds__(256) convert_bank_kernel(const float* __restrict__ bank) {
    int tid = threadIdx.x;
    if (blockIdx.x == 0 && tid < (NPAD - NPIX)) g_min[NPIX + tid] = 0x7f800000u;
    int wid  = (blockIdx.x * 256 + tid) >> 5;
    int lane = tid & 31;
    int nw = (gridDim.x * 256) >> 5;
    for (int r = wid; r < MB_PAD; r += nw) {
        if (r < MB_N) {
            const float* row = bank + (size_t)r * E_DIM;
            __half* orow = g_bank_h + (size_t)r * E_DIM;
            float s = 0.f;
            for (int k = lane * 8; k < E_DIM; k += 256) {
                float4 a = *(const float4*)(row + k);
                float4 b = *(const float4*)(row + k + 4);
                s += a.x*a.x + a.y*a.y + a.z*a.z + a.w*a.w;
                s += b.x*b.x + b.y*b.y + b.z*b.z + b.w*b.w;
                __half2 h0 = __floats2half2_rn(a.x, a.y);
                __half2 h1 = __floats2half2_rn(a.z, a.w);
                __half2 h2 = __floats2half2_rn(b.x, b.y);
                __half2 h3 = __floats2half2_rn(b.z, b.w);
                uint4 o;
                o.x = *(unsigned int*)&h0;
                o.y = *(unsigned int*)&h1;
                o.z = *(unsigned int*)&h2;
                o.w = *(unsigned int*)&h3;
                *(uint4*)(orow + k) = o;
            }
            #pragma unroll
            for (int off = 16; off > 0; off >>= 1)
                s += __shfl_xor_sync(0xffffffffu, s, off);
            if (lane == 0) g_bank_norm[r] = s;
        } else {
            if (lane == 0) g_bank_norm[r] = 1e30f;
        }
    }
}

// ---------------- 3) fp16 mma.sync distance GEMM + fused min ----------------
// grid (7, 782). x<6: full 128-row path (no pad). x==6: 16-row tail path
// (rows 768..783): 1 m-frag, 8 warps x 16 cols, 1/16 the MMA work.
__global__ void __launch_bounds__(256, 2) distmin_mma_kernel() {
    extern __shared__ char smem[];
    uint32_t smem_u32;
    asm("{ .reg .u64 t; cvta.to.shared.u64 t, %1; cvt.u32.u64 %0, t; }"
        : "=r"(smem_u32) : "l"(smem));

    const int tid  = threadIdx.x;
    const int wid  = tid >> 5;
    const int lane = tid & 31;
    const int n0 = blockIdx.y * 128;

    const int g   = lane >> 3;
    const int lr  = lane & 7;
    const int a_row = lr + (g & 1) * 8;
    const int a_kb  = (g >> 1) * 16;
    const int b_row = lr + (g >> 1) * 8;
    const int b_kb  = (g & 1) * 16;
    const int qid = lane >> 2;
    const int qtd = lane & 3;

    if (blockIdx.x < 6) {
        // ================= full path (identical to R13) =================
        const int m0 = blockIdx.x * 128;
        const int wm = wid >> 2;
        const int wn = wid & 3;
        const int m_base = wm * 64;
        const int n_base = wn * 32;

        uint32_t hacc[4][4][2];
        #pragma unroll
        for (int i = 0; i < 4; i++)
            #pragma unroll
            for (int j = 0; j < 4; j++) {
                hacc[i][j][0] = 0u;
                hacc[i][j][1] = 0u;
            }

        auto issue = [&](int it) {
            uint32_t sb = smem_u32 + (uint32_t)(it % STG) * STAGE_B;
            int kk = it * BK;
            const __half* abase = g_emb_h + (size_t)m0 * E_DIM + kk;
            #pragma unroll
            for (int i = 0; i < 4; i++) {
                int f = tid + i * 256;
                int r = f >> 3, c = f & 7;
                cpasync16(sb + r * ROWB + c * 16, abase + (size_t)r * E_DIM + c * 8);
            }
            const __half* bbase = g_bank_h + (size_t)n0 * E_DIM + kk;
            #pragma unroll
            for (int i = 0; i < 4; i++) {
                int f = tid + i * 256;
                int r = f >> 3, c = f & 7;
                cpasync16(sb + TILE_B + r * ROWB + c * 16, bbase + (size_t)r * E_DIM + c * 8);
            }
            asm volatile("cp.async.commit_group;" ::: "memory");
        };

        issue(0);
        issue(1);

        for (int it = 0; it < NKS; it++) {
            if (it < NKS - 1) asm volatile("cp.async.wait_group 1;" ::: "memory");
            else              asm volatile("cp.async.wait_group 0;" ::: "memory");
            __syncthreads();
            if (it + 2 < NKS) issue(it + 2);

            uint32_t sa = smem_u32 + (uint32_t)(it % STG) * STAGE_B;
            uint32_t sbb = sa + TILE_B;
            #pragma unroll
            for (int ks = 0; ks < 4; ks++) {
                uint32_t a[4][4];
                #pragma unroll
                for (int mi = 0; mi < 4; mi++)
                    ldsm4(a[mi], sa + (uint32_t)(m_base + mi * 16 + a_row) * ROWB + ks * 32 + a_kb);
                uint32_t b[2][4];
                #pragma unroll
                for (int p = 0; p < 2; p++)
                    ldsm4(b[p], sbb + (uint32_t)(n_base + p * 16 + b_row) * ROWB + ks * 32 + b_kb);
                #pragma unroll
                for (int mi = 0; mi < 4; mi++) {
                    #pragma unroll
                    for (int ni = 0; ni < 4; ni++)
                        mma16816h(hacc[mi][ni], a[mi], b[ni >> 1][(ni & 1) * 2],
                                  b[ni >> 1][(ni & 1) * 2 + 1]);
                }
            }
        }

        float bnv[4][2];
        #pragma unroll
        for (int ni = 0; ni < 4; ni++) {
            int n = n0 + n_base + ni * 8 + qtd * 2;
            bnv[ni][0] = g_bank_norm[n];
            bnv[ni][1] = g_bank_norm[n + 1];
        }
        #pragma unroll
        for (int mi = 0; mi < 4; mi++) {
            int r0 = m0 + m_base + mi * 16 + qid;
            int r1 = r0 + 8;
            float rn0 = g_row_norm[r0];
            float rn1 = g_row_norm[r1];
            float min0 = 1e30f, min1 = 1e30f;
            #pragma unroll
            for (int ni = 0; ni < 4; ni++) {
                float2 lo = __half22float2(*(__half2*)&hacc[mi][ni][0]);
                float2 hi = __half22float2(*(__half2*)&hacc[mi][ni][1]);
                min0 = fminf(min0, fmaxf(rn0 + bnv[ni][0] - 2.f * lo.x, 0.f));
                min0 = fminf(min0, fmaxf(rn0 + bnv[ni][1] - 2.f * lo.y, 0.f));
                min1 = fminf(min1, fmaxf(rn1 + bnv[ni][0] - 2.f * hi.x, 0.f));
                min1 = fminf(min1, fmaxf(rn1 + bnv[ni][1] - 2.f * hi.y, 0.f));
            }
            min0 = fminf(min0, __shfl_xor_sync(0xffffffffu, min0, 1));
            min0 = fminf(min0, __shfl_xor_sync(0xffffffffu, min0, 2));
            min1 = fminf(min1, __shfl_xor_sync(0xffffffffu, min1, 1));
            min1 = fminf(min1, __shfl_xor_sync(0xffffffffu, min1, 2));
            if (qtd == 0) {
                atomicMin(&g_min[r0], __float_as_uint(min0));
                atomicMin(&g_min[r1], __float_as_uint(min1));
            }
        }
    } else {
        // ================= tail path: rows 768..783 =================
        const int nb = wid * 16;    // 8 warps x 16 cols
        uint32_t tacc[2][2] = {{0u, 0u}, {0u, 0u}};

        auto issueT = [&](int it) {
            uint32_t sb = smem_u32 + (uint32_t)(it % STG) * STAGE_B;
            int kk = it * BK;
            const __half* abase = g_emb_h + (size_t)768 * E_DIM + kk;
            if (tid < 128) {            // 16 rows x 8 chunks
                int r = tid >> 3, c = tid & 7;
                cpasync16(sb + r * ROWB + c * 16, abase + (size_t)r * E_DIM + c * 8);
            }
            const __half* bbase = g_bank_h + (size_t)n0 * E_DIM + kk;
            #pragma unroll
            for (int i = 0; i < 4; i++) {
                int f = tid + i * 256;
                int r = f >> 3, c = f & 7;
                cpasync16(sb + TILE_B + r * ROWB + c * 16, bbase + (size_t)r * E_DIM + c * 8);
            }
            asm volatile("cp.async.commit_group;" ::: "memory");
        };

        issueT(0);
        issueT(1);

        for (int it = 0; it < NKS; it++) {
            if (it < NKS - 1) asm volatile("cp.async.wait_group 1;" ::: "memory");
            else              asm volatile("cp.async.wait_group 0;" ::: "memory");
            __syncthreads();
            if (it + 2 < NKS) issueT(it + 2);

            uint32_t sa = smem_u32 + (uint32_t)(it % STG) * STAGE_B;
            uint32_t sbb = sa + TILE_B;
            #pragma unroll
            for (int ks = 0; ks < 4; ks++) {
                uint32_t a[4];
                ldsm4(a, sa + (uint32_t)(a_row) * ROWB + ks * 32 + a_kb);
                uint32_t b[4];
                ldsm4(b, sbb + (uint32_t)(nb + b_row) * ROWB + ks * 32 + b_kb);
                mma16816h(tacc[0], a, b[0], b[1]);
                mma16816h(tacc[1], a, b[2], b[3]);
            }
        }

        float bnv[2][2];
        #pragma unroll
        for (int ni = 0; ni < 2; ni++) {
            int n = n0 + nb + ni * 8 + qtd * 2;
            bnv[ni][0] = g_bank_norm[n];
            bnv[ni][1] = g_bank_norm[n + 1];
        }
        int r0 = 768 + qid;
        int r1 = 768 + 8 + qid;
        float rn0 = g_row_norm[r0];
        float rn1 = g_row_norm[r1];
        float min0 = 1e30f, min1 = 1e30f;
        #pragma unroll
        for (int ni = 0; ni < 2; ni++) {
            float2 lo = __half22float2(*(__half2*)&tacc[ni][0]);
            float2 hi = __half22float2(*(__half2*)&tacc[ni][1]);
            min0 = fminf(min0, fmaxf(rn0 + bnv[ni][0] - 2.f * lo.x, 0.f));
            min0 = fminf(min0, fmaxf(rn0 + bnv[ni][1] - 2.f * lo.y, 0.f));
            min1 = fminf(min1, fmaxf(rn1 + bnv[ni][0] - 2.f * hi.x, 0.f));
            min1 = fminf(min1, fmaxf(rn1 + bnv[ni][1] - 2.f * hi.y, 0.f));
        }
        min0 = fminf(min0, __shfl_xor_sync(0xffffffffu, min0, 1));
        min0 = fminf(min0, __shfl_xor_sync(0xffffffffu, min0, 2));
        min1 = fminf(min1, __shfl_xor_sync(0xffffffffu, min1, 1));
        min1 = fminf(min1, __shfl_xor_sync(0xffffffffu, min1, 2));
        if (qtd == 0) {
            atomicMin(&g_min[r0], __float_as_uint(min0));
            atomicMin(&g_min[r1], __float_as_uint(min1));
        }
    }
}

// ---------------- 4) sqrt scores + argmax ----------------
__global__ void __launch_bounds__(1024) scores_kernel() {
    __shared__ float sv[1024];
    __shared__ int   si[1024];
    int tid = threadIdx.x;
    float s = -1e30f;
    if (tid < NPIX) {
        float d2 = __uint_as_float(g_min[tid]);
        s = sqrtf(fmaxf(d2, 1e-12f));
        g_amap28[tid] = s;
    }
    sv[tid] = s;
    si[tid] = tid;
    __syncthreads();
    for (int off = 512; off > 0; off >>= 1) {
        if (tid < off) {
            if (sv[tid + off] > sv[tid]) { sv[tid] = sv[tid + off]; si[tid] = si[tid + off]; }
        }
        __syncthreads();
    }
    if (tid == 0) g_argmax = si[0];
}

// ---------------- 5) argmax-row distances (fp32 emb x fp16 bank, fp32 acc) ----
__global__ void __launch_bounds__(256) row_dist_kernel() {
    __shared__ float e[E_DIM];
    int tid = threadIdx.x;
    int rstar = g_argmax;
    for (int i = tid; i < E_DIM; i += 256)
        e[i] = g_emb[(size_t)rstar * E_DIM + i];
    __syncthreads();
    float rn = g_row_norm[rstar];
    int wid  = (blockIdx.x * 256 + tid) >> 5;
    int lane = tid & 31;
    int nw = (gridDim.x * 256) >> 5;
    for (int r = wid; r < MB_N; r += nw) {
        const __half* row = g_bank_h + (size_t)r * E_DIM;
        uint4 u[6];
        #pragma unroll
        for (int j = 0; j < 6; j++)
            u[j] = *(const uint4*)(row + lane * 8 + j * 256);
        float s = 0.f;
        #pragma unroll
        for (int j = 0; j < 6; j++) {
            int k = lane * 8 + j * 256;
            float2 f0 = __half22float2(*(__half2*)&u[j].x);
            float2 f1 = __half22float2(*(__half2*)&u[j].y);
            float2 f2 = __half22float2(*(__half2*)&u[j].z);
            float2 f3 = __half22float2(*(__half2*)&u[j].w);
            s += f0.x * e[k]     + f0.y * e[k + 1] + f1.x * e[k + 2] + f1.y * e[k + 3];
            s += f2.x * e[k + 4] + f2.y * e[k + 5] + f3.x * e[k + 6] + f3.y * e[k + 7];
        }
        #pragma unroll
        for (int off = 16; off > 0; off >>= 1)
            s += __shfl_xor_sync(0xffffffffu, s, off);
        if (lane == 0)
            g_d2row[r] = fmaxf(rn + g_bank_norm[r] - 2.f * s, 0.f);
    }
}

// ---------------- 6) top-9 + anomaly score ----------------
__global__ void __launch_bounds__(1024) top9_kernel(float* __restrict__ out, int out_size) {
    __shared__ float s[1024 * 9];
    __shared__ float rv[1024];
    __shared__ int   ri[1024];
    __shared__ float cf[9];
    int tid = threadIdx.x;

    float t[9];
    #pragma unroll
    for (int i = 0; i < 9; i++) t[i] = __int_as_float(0x7f800000);
    for (int j = tid; j < MB_N; j += 1024) {
        float v = g_d2row[j];
        if (v < t[8]) {
            t[8] = v;
            #pragma unroll
            for (int i = 8; i > 0; i--) {
                float a = fminf(t[i - 1], t[i]);
                float b = fmaxf(t[i - 1], t[i]);
                t[i - 1] = a; t[i] = b;
            }
        }
    }
    #pragma unroll
    for (int i = 0; i < 9; i++) s[tid * 9 + i] = t[i];
    __syncthreads();

    for (int r = 0; r < 9; r++) {
        float lv = __int_as_float(0x7f800000);
        int   li = -1;
        #pragma unroll
        for (int i = 0; i < 9; i++) {
            float v = s[tid * 9 + i];
            if (v < lv) { lv = v; li = tid * 9 + i; }
        }
        rv[tid] = lv; ri[tid] = li;
        __syncthreads();
        for (int off = 512; off > 0; off >>= 1) {
            if (tid < off) {
                if (rv[tid + off] < rv[tid]) { rv[tid] = rv[tid + off]; ri[tid] = ri[tid + off]; }
            }
            __syncthreads();
        }
        if (tid == 0) {
            cf[r] = sqrtf(fmaxf(rv[0], 1e-12f));
            s[ri[0]] = __int_as_float(0x7f800000);
        }
        __syncthreads();
    }

    if (tid == 0) {
        double emax = exp((double)cf[8]);
        double sum = 0.0;
        #pragma unroll
        for (int i = 0; i < 9; i++) sum += exp((double)cf[i]);
        double weight = 1.0 - emax / sum;
        out[out_size - 1] = (float)(weight * (double)cf[0]);
    }
}

// ---------------- 7) bilinear resize 28 -> 224 ----------------
__global__ void __launch_bounds__(256) resize_kernel() {
    int o = blockIdx.x * 256 + threadIdx.x;
    if (o >= OUTPIX) return;
    int oy = o / OUTHW, ox = o % OUTHW;
    float fy = oy * 0.125f - 0.4375f;
    float fx = ox * 0.125f - 0.4375f;
    int y0 = (int)floorf(fy);
    int x0 = (int)floorf(fx);
    float wy = fy - (float)y0;
    float wx = fx - (float)x0;
    int y0c = min(max(y0, 0), 27), y1c = min(max(y0 + 1, 0), 27);
    int x0c = min(max(x0, 0), 27), x1c = min(max(x0 + 1, 0), 27);
    float v00 = g_amap28[y0c * 28 + x0c];
    float v01 = g_amap28[y0c * 28 + x1c];
    float v10 = g_amap28[y1c * 28 + x0c];
    float v11 = g_amap28[y1c * 28 + x1c];
    g_t0[o] = (1.f - wy) * ((1.f - wx) * v00 + wx * v01)
            + wy * ((1.f - wx) * v10 + wx * v11);
}

// ---------------- 8/9) separable gaussian ----------------
__device__ __forceinline__ int refl224(int i) {
    if (i < 0) return -1 - i;
    if (i > 223) return 447 - i;
    return i;
}

__global__ void __launch_bounds__(256) gaussv_kernel() {
    __shared__ float w[33];
    int tid = threadIdx.x;
    if (tid < 33) {
        float d = (float)tid - 16.f;
        w[tid] = expf(-d * d / 32.f);
    }
    __syncthreads();
    float Z = 0.f;
    #pragma unroll
    for (int i = 0; i < 33; i++) Z += w[i];
    float inv = 1.f / Z;
    int o = blockIdx.x * 256 + tid;
    if (o >= OUTPIX) return;
    int y = o / OUTHW, x = o % OUTHW;
    float s = 0.f;
    #pragma unroll
    for (int d = 0; d < 33; d++) {
        int yy = refl224(y + d - 16);
        s += w[d] * g_t0[yy * OUTHW + x];
    }
    g_t1[o] = s * inv;
}

__global__ void __launch_bounds__(256) gaussh_kernel(float* __restrict__ out) {
    __shared__ float w[33];
    int tid = threadIdx.x;
    if (tid < 33) {
        float d = (float)tid - 16.f;
        w[tid] = expf(-d * d / 32.f);
    }
    __syncthreads();
    float Z = 0.f;
    #pragma unroll
    for (int i = 0; i < 33; i++) Z += w[i];
    float inv = 1.f / Z;
    int o = blockIdx.x * 256 + tid;
    if (o >= OUTPIX) return;
    int y = o / OUTHW, x = o % OUTHW;
    float s = 0.f;
    #pragma unroll
    for (int d = 0; d < 33; d++) {
        int xx = refl224(x + d - 16);
        s += w[d] * g_t1[y * OUTHW + xx];
    }
    out[o] = s * inv;
}

// ---------------- launch ----------------
extern "C" void kernel_launch(void* const* d_in, const int* in_sizes, int n_in,
                              void* d_out, int out_size) {
    const float* f2   = (const float*)d_in[0];
    const float* f3   = (const float*)d_in[1];
    const float* bank = (const float*)d_in[2];
    float* out = (float*)d_out;

    cudaFuncSetAttribute(distmin_mma_kernel,
                         cudaFuncAttributeMaxDynamicSharedMemorySize, SMEM_REQ);

    embed_kernel<<<NPIX, 256>>>(f2, f3);
    convert_bank_kernel<<<1184, 256>>>(bank);

    dim3 g(7, MB_PAD / 128);   // x<6: full 128-row tiles; x==6: 16-row tail
    distmin_mma_kernel<<<g, 256, SMEM_REQ>>>();

    scores_kernel<<<1, 1024>>>();
    row_dist_kernel<<<1563, 256>>>();
    top9_kernel<<<1, 1024>>>(out, out_size);

    resize_kernel<<<(OUTPIX + 255) / 256, 256>>>();
    gaussv_kernel<<<(OUTPIX + 255) / 256, 256>>>();
    gaussh_kernel<<<(OUTPIX + 255) / 256, 256>>>(out);
}

// round 16
// speedup vs baseline: 1.0716x; 1.0048x over previous
#include <cuda_runtime.h>
#include <cuda_fp16.h>
#include <stdint.h>
#include <math.h>

#define MB_N    100000
#define MB_PAD  100096          // 782 * 128
#define E_DIM   1536
#define NPIX    784
#define NPAD    896
#define OUTHW   224
#define OUTPIX  (224*224)

// ---- mma GEMM tiling (R6 schedule, fp16 data + fp16 accumulate) ----
#define BK      64
#define NKS     (E_DIM / BK)    // 24
#define STG     3
#define ROWB    144             // bytes per smem row (128B data + 16B pad)
#define TILE_B  (128 * ROWB)    // 18432
#define STAGE_B (2 * TILE_B)    // 36864
#define SMEM_REQ (STG * STAGE_B)  // 110592

// ---------------- device scratch ----------------
__device__ float         g_emb[NPIX * E_DIM];
__device__ __half        g_emb_h[NPAD * E_DIM];             // pad rows stay zero
__device__ __half        g_bank_h[(size_t)MB_PAD * E_DIM];  // pad rows stay zero
__device__ float         g_row_norm[NPAD];
__device__ float         g_bank_norm[MB_PAD];               // pad rows = 1e30
__device__ unsigned int  g_min[NPAD];
__device__ float         g_d2row[MB_N];
__device__ int           g_argmax;
__device__ float         g_amap28[NPIX];
__device__ float         g_t0[OUTPIX];
__device__ float         g_t1[OUTPIX];

// ---------------- helpers ----------------
__device__ __forceinline__ void cpasync16(uint32_t dst, const void* src) {
    asm volatile("cp.async.cg.shared.global [%0], [%1], 16;" :: "r"(dst), "l"(src));
}

__device__ __forceinline__ void ldsm4(uint32_t (&r)[4], uint32_t addr) {
    asm volatile("ldmatrix.sync.aligned.m8n8.x4.shared.b16 {%0,%1,%2,%3}, [%4];"
                 : "=r"(r[0]), "=r"(r[1]), "=r"(r[2]), "=r"(r[3]) : "r"(addr));
}

__device__ __forceinline__ void mma16816h(uint32_t (&d)[2], const uint32_t (&a)[4],
                                          uint32_t b0, uint32_t b1) {
    asm volatile(
        "mma.sync.aligned.m16n8k16.row.col.f16.f16.f16.f16 "
        "{%0,%1}, {%2,%3,%4,%5}, {%6,%7}, {%0,%1};"
        : "+r"(d[0]), "+r"(d[1])
        : "r"(a[0]), "r"(a[1]), "r"(a[2]), "r"(a[3]), "r"(b0), "r"(b1));
}

// ---------------- 1) embedding + row norms + fp16 copy ----------------
__global__ void __launch_bounds__(256) embed_kernel(const float* __restrict__ f2,
                                                    const float* __restrict__ f3) {
    __shared__ float red[256];
    int p = blockIdx.x;
    int y = p / 28, x = p % 28;
    int tid = threadIdx.x;
    float ss = 0.f;

    for (int c = tid; c < 512; c += 256) {
        const float* base = f2 + c * 784;
        float s = 0.f;
        #pragma unroll
        for (int dy = -1; dy <= 1; dy++) {
            int yy = y + dy;
            if (yy < 0 || yy >= 28) continue;
            #pragma unroll
            for (int dx = -1; dx <= 1; dx++) {
                int xx = x + dx;
                if (xx < 0 || xx >= 28) continue;
                s += base[yy * 28 + xx];
            }
        }
        float v = s * (1.f / 9.f);
        g_emb[p * E_DIM + c] = v;
        g_emb_h[(size_t)p * E_DIM + c] = __float2half_rn(v);
        ss += v * v;
    }
    int y2 = y >> 1, x2 = x >> 1;
    for (int c = tid; c < 1024; c += 256) {
        const float* base = f3 + c * 196;
        float s = 0.f;
        #pragma unroll
        for (int dy = -1; dy <= 1; dy++) {
            int yy = y2 + dy;
            if (yy < 0 || yy >= 14) continue;
            #pragma unroll
            for (int dx = -1; dx <= 1; dx++) {
                int xx = x2 + dx;
                if (xx < 0 || xx >= 14) continue;
                s += base[yy * 14 + xx];
            }
        }
        float v = s * (1.f / 9.f);
        g_emb[p * E_DIM + 512 + c] = v;
        g_emb_h[(size_t)p * E_DIM + 512 + c] = __float2half_rn(v);
        ss += v * v;
    }
    red[tid] = ss;
    __syncthreads();
    for (int off = 128; off > 0; off >>= 1) {
        if (tid < off) red[tid] += red[tid + off];
        __syncthreads();
    }
    if (tid == 0) {
        g_row_norm[p] = red[0];
        g_min[p] = 0x7f800000u;
    }
}

// ---------------- 2) bank fp32 -> fp16 + norms — MLP-batched ----------------
__global__ void __launch_bounds__(256) convert_bank_kernel(const float* __restrict__ bank) {
    int tid = threadIdx.x;
    if (blockIdx.x == 0 && tid < (NPAD - NPIX)) g_min[NPIX + tid] = 0x7f800000u;
    int wid  = (blockIdx.x * 256 + tid) >> 5;
    int lane = tid & 31;
    int nw = (gridDim.x * 256) >> 5;
    for (int r = wid; r < MB_PAD; r += nw) {
        if (r < MB_N) {
            const float* row = bank + (size_t)r * E_DIM;
            __half* orow = g_bank_h + (size_t)r * E_DIM;
            // batch all 12 independent float4 loads first (MLP 12)
            float4 v[12];
            #pragma unroll
            for (int j = 0; j < 6; j++) {
                int k = lane * 8 + j * 256;
                v[2 * j]     = *(const float4*)(row + k);
                v[2 * j + 1] = *(const float4*)(row + k + 4);
            }
            float s = 0.f;
            #pragma unroll
            for (int j = 0; j < 6; j++) {
                int k = lane * 8 + j * 256;
                float4 a = v[2 * j];
                float4 b = v[2 * j + 1];
                s += a.x*a.x + a.y*a.y + a.z*a.z + a.w*a.w;
                s += b.x*b.x + b.y*b.y + b.z*b.z + b.w*b.w;
                __half2 h0 = __floats2half2_rn(a.x, a.y);
                __half2 h1 = __floats2half2_rn(a.z, a.w);
                __half2 h2 = __floats2half2_rn(b.x, b.y);
                __half2 h3 = __floats2half2_rn(b.z, b.w);
                uint4 o;
                o.x = *(unsigned int*)&h0;
                o.y = *(unsigned int*)&h1;
                o.z = *(unsigned int*)&h2;
                o.w = *(unsigned int*)&h3;
                *(uint4*)(orow + k) = o;
            }
            #pragma unroll
            for (int off = 16; off > 0; off >>= 1)
                s += __shfl_xor_sync(0xffffffffu, s, off);
            if (lane == 0) g_bank_norm[r] = s;
        } else {
            if (lane == 0) g_bank_norm[r] = 1e30f;
        }
    }
}

// ---------------- 3) fp16 mma.sync distance GEMM + fused min ----------------
// grid (7, 782). x<6: full 128-row path. x==6: 16-row tail (rows 768..783).
__global__ void __launch_bounds__(256, 2) distmin_mma_kernel() {
    extern __shared__ char smem[];
    uint32_t smem_u32;
    asm("{ .reg .u64 t; cvta.to.shared.u64 t, %1; cvt.u32.u64 %0, t; }"
        : "=r"(smem_u32) : "l"(smem));

    const int tid  = threadIdx.x;
    const int wid  = tid >> 5;
    const int lane = tid & 31;
    const int n0 = blockIdx.y * 128;

    const int g   = lane >> 3;
    const int lr  = lane & 7;
    const int a_row = lr + (g & 1) * 8;
    const int a_kb  = (g >> 1) * 16;
    const int b_row = lr + (g >> 1) * 8;
    const int b_kb  = (g & 1) * 16;
    const int qid = lane >> 2;
    const int qtd = lane & 3;

    if (blockIdx.x < 6) {
        const int m0 = blockIdx.x * 128;
        const int wm = wid >> 2;
        const int wn = wid & 3;
        const int m_base = wm * 64;
        const int n_base = wn * 32;

        uint32_t hacc[4][4][2];
        #pragma unroll
        for (int i = 0; i < 4; i++)
            #pragma unroll
            for (int j = 0; j < 4; j++) {
                hacc[i][j][0] = 0u;
                hacc[i][j][1] = 0u;
            }

        auto issue = [&](int it) {
            uint32_t sb = smem_u32 + (uint32_t)(it % STG) * STAGE_B;
            int kk = it * BK;
            const __half* abase = g_emb_h + (size_t)m0 * E_DIM + kk;
            #pragma unroll
            for (int i = 0; i < 4; i++) {
                int f = tid + i * 256;
                int r = f >> 3, c = f & 7;
                cpasync16(sb + r * ROWB + c * 16, abase + (size_t)r * E_DIM + c * 8);
            }
            const __half* bbase = g_bank_h + (size_t)n0 * E_DIM + kk;
            #pragma unroll
            for (int i = 0; i < 4; i++) {
                int f = tid + i * 256;
                int r = f >> 3, c = f & 7;
                cpasync16(sb + TILE_B + r * ROWB + c * 16, bbase + (size_t)r * E_DIM + c * 8);
            }
            asm volatile("cp.async.commit_group;" ::: "memory");
        };

        issue(0);
        issue(1);

        for (int it = 0; it < NKS; it++) {
            if (it < NKS - 1) asm volatile("cp.async.wait_group 1;" ::: "memory");
            else              asm volatile("cp.async.wait_group 0;" ::: "memory");
            __syncthreads();
            if (it + 2 < NKS) issue(it + 2);

            uint32_t sa = smem_u32 + (uint32_t)(it % STG) * STAGE_B;
            uint32_t sbb = sa + TILE_B;
            #pragma unroll
            for (int ks = 0; ks < 4; ks++) {
                uint32_t a[4][4];
                #pragma unroll
                for (int mi = 0; mi < 4; mi++)
                    ldsm4(a[mi], sa + (uint32_t)(m_base + mi * 16 + a_row) * ROWB + ks * 32 + a_kb);
                uint32_t b[2][4];
                #pragma unroll
                for (int p = 0; p < 2; p++)
                    ldsm4(b[p], sbb + (uint32_t)(n_base + p * 16 + b_row) * ROWB + ks * 32 + b_kb);
                #pragma unroll
                for (int mi = 0; mi < 4; mi++) {
                    #pragma unroll
                    for (int ni = 0; ni < 4; ni++)
                        mma16816h(hacc[mi][ni], a[mi], b[ni >> 1][(ni & 1) * 2],
                                  b[ni >> 1][(ni & 1) * 2 + 1]);
                }
            }
        }

        float bnv[4][2];
        #pragma unroll
        for (int ni = 0; ni < 4; ni++) {
            int n = n0 + n_base + ni * 8 + qtd * 2;
            bnv[ni][0] = g_bank_norm[n];
            bnv[ni][1] = g_bank_norm[n + 1];
        }
        #pragma unroll
        for (int mi = 0; mi < 4; mi++) {
            int r0 = m0 + m_base + mi * 16 + qid;
            int r1 = r0 + 8;
            float rn0 = g_row_norm[r0];
            float rn1 = g_row_norm[r1];
            float min0 = 1e30f, min1 = 1e30f;
            #pragma unroll
            for (int ni = 0; ni < 4; ni++) {
                float2 lo = __half22float2(*(__half2*)&hacc[mi][ni][0]);
                float2 hi = __half22float2(*(__half2*)&hacc[mi][ni][1]);
                min0 = fminf(min0, fmaxf(rn0 + bnv[ni][0] - 2.f * lo.x, 0.f));
                min0 = fminf(min0, fmaxf(rn0 + bnv[ni][1] - 2.f * lo.y, 0.f));
                min1 = fminf(min1, fmaxf(rn1 + bnv[ni][0] - 2.f * hi.x, 0.f));
                min1 = fminf(min1, fmaxf(rn1 + bnv[ni][1] - 2.f * hi.y, 0.f));
            }
            min0 = fminf(min0, __shfl_xor_sync(0xffffffffu, min0, 1));
            min0 = fminf(min0, __shfl_xor_sync(0xffffffffu, min0, 2));
            min1 = fminf(min1, __shfl_xor_sync(0xffffffffu, min1, 1));
            min1 = fminf(min1, __shfl_xor_sync(0xffffffffu, min1, 2));
            if (qtd == 0) {
                atomicMin(&g_min[r0], __float_as_uint(min0));
                atomicMin(&g_min[r1], __float_as_uint(min1));
            }
        }
    } else {
        // tail: rows 768..783
        const int nb = wid * 16;
        uint32_t tacc[2][2] = {{0u, 0u}, {0u, 0u}};

        auto issueT = [&](int it) {
            uint32_t sb = smem_u32 + (uint32_t)(it % STG) * STAGE_B;
            int kk = it * BK;
            const __half* abase = g_emb_h + (size_t)768 * E_DIM + kk;
            if (tid < 128) {
                int r = tid >> 3, c = tid & 7;
                cpasync16(sb + r * ROWB + c * 16, abase + (size_t)r * E_DIM + c * 8);
            }
            const __half* bbase = g_bank_h + (size_t)n0 * E_DIM + kk;
            #pragma unroll
            for (int i = 0; i < 4; i++) {
                int f = tid + i * 256;
                int r = f >> 3, c = f & 7;
                cpasync16(sb + TILE_B + r * ROWB + c * 16, bbase + (size_t)r * E_DIM + c * 8);
            }
            asm volatile("cp.async.commit_group;" ::: "memory");
        };

        issueT(0);
        issueT(1);

        for (int it = 0; it < NKS; it++) {
            if (it < NKS - 1) asm volatile("cp.async.wait_group 1;" ::: "memory");
            else              asm volatile("cp.async.wait_group 0;" ::: "memory");
            __syncthreads();
            if (it + 2 < NKS) issueT(it + 2);

            uint32_t sa = smem_u32 + (uint32_t)(it % STG) * STAGE_B;
            uint32_t sbb = sa + TILE_B;
            #pragma unroll
            for (int ks = 0; ks < 4; ks++) {
                uint32_t a[4];
                ldsm4(a, sa + (uint32_t)(a_row) * ROWB + ks * 32 + a_kb);
                uint32_t b[4];
                ldsm4(b, sbb + (uint32_t)(nb + b_row) * ROWB + ks * 32 + b_kb);
                mma16816h(tacc[0], a, b[0], b[1]);
                mma16816h(tacc[1], a, b[2], b[3]);
            }
        }

        float bnv[2][2];
        #pragma unroll
        for (int ni = 0; ni < 2; ni++) {
            int n = n0 + nb + ni * 8 + qtd * 2;
            bnv[ni][0] = g_bank_norm[n];
            bnv[ni][1] = g_bank_norm[n + 1];
        }
        int r0 = 768 + qid;
        int r1 = 768 + 8 + qid;
        float rn0 = g_row_norm[r0];
        float rn1 = g_row_norm[r1];
        float min0 = 1e30f, min1 = 1e30f;
        #pragma unroll
        for (int ni = 0; ni < 2; ni++) {
            float2 lo = __half22float2(*(__half2*)&tacc[ni][0]);
            float2 hi = __half22float2(*(__half2*)&tacc[ni][1]);
            min0 = fminf(min0, fmaxf(rn0 + bnv[ni][0] - 2.f * lo.x, 0.f));
            min0 = fminf(min0, fmaxf(rn0 + bnv[ni][1] - 2.f * lo.y, 0.f));
            min1 = fminf(min1, fmaxf(rn1 + bnv[ni][0] - 2.f * hi.x, 0.f));
            min1 = fminf(min1, fmaxf(rn1 + bnv[ni][1] - 2.f * hi.y, 0.f));
        }
        min0 = fminf(min0, __shfl_xor_sync(0xffffffffu, min0, 1));
        min0 = fminf(min0, __shfl_xor_sync(0xffffffffu, min0, 2));
        min1 = fminf(min1, __shfl_xor_sync(0xffffffffu, min1, 1));
        min1 = fminf(min1, __shfl_xor_sync(0xffffffffu, min1, 2));
        if (qtd == 0) {
            atomicMin(&g_min[r0], __float_as_uint(min0));
            atomicMin(&g_min[r1], __float_as_uint(min1));
        }
    }
}

// ---------------- 4) sqrt scores + argmax ----------------
__global__ void __launch_bounds__(1024) scores_kernel() {
    __shared__ float sv[1024];
    __shared__ int   si[1024];
    int tid = threadIdx.x;
    float s = -1e30f;
    if (tid < NPIX) {
        float d2 = __uint_as_float(g_min[tid]);
        s = sqrtf(fmaxf(d2, 1e-12f));
        g_amap28[tid] = s;
    }
    sv[tid] = s;
    si[tid] = tid;
    __syncthreads();
    for (int off = 512; off > 0; off >>= 1) {
        if (tid < off) {
            if (sv[tid + off] > sv[tid]) { sv[tid] = sv[tid + off]; si[tid] = si[tid + off]; }
        }
        __syncthreads();
    }
    if (tid == 0) g_argmax = si[0];
}

// ---------------- 5) argmax-row distances (fp32 emb x fp16 bank, fp32 acc) ----
__global__ void __launch_bounds__(256) row_dist_kernel() {
    __shared__ float e[E_DIM];
    int tid = threadIdx.x;
    int rstar = g_argmax;
    for (int i = tid; i < E_DIM; i += 256)
        e[i] = g_emb[(size_t)rstar * E_DIM + i];
    __syncthreads();
    float rn = g_row_norm[rstar];
    int wid  = (blockIdx.x * 256 + tid) >> 5;
    int lane = tid & 31;
    int nw = (gridDim.x * 256) >> 5;
    for (int r = wid; r < MB_N; r += nw) {
        const __half* row = g_bank_h + (size_t)r * E_DIM;
        uint4 u[6];
        #pragma unroll
        for (int j = 0; j < 6; j++)
            u[j] = *(const uint4*)(row + lane * 8 + j * 256);
        float s = 0.f;
        #pragma unroll
        for (int j = 0; j < 6; j++) {
            int k = lane * 8 + j * 256;
            float2 f0 = __half22float2(*(__half2*)&u[j].x);
            float2 f1 = __half22float2(*(__half2*)&u[j].y);
            float2 f2 = __half22float2(*(__half2*)&u[j].z);
            float2 f3 = __half22float2(*(__half2*)&u[j].w);
            s += f0.x * e[k]     + f0.y * e[k + 1] + f1.x * e[k + 2] + f1.y * e[k + 3];
            s += f2.x * e[k + 4] + f2.y * e[k + 5] + f3.x * e[k + 6] + f3.y * e[k + 7];
        }
        #pragma unroll
        for (int off = 16; off > 0; off >>= 1)
            s += __shfl_xor_sync(0xffffffffu, s, off);
        if (lane == 0)
            g_d2row[r] = fmaxf(rn + g_bank_norm[r] - 2.f * s, 0.f);
    }
}

// ---------------- 6) top-9 + anomaly score ----------------
__global__ void __launch_bounds__(1024) top9_kernel(float* __restrict__ out, int out_size) {
    __shared__ float s[1024 * 9];
    __shared__ float rv[1024];
    __shared__ int   ri[1024];
    __shared__ float cf[9];
    int tid = threadIdx.x;

    float t[9];
    #pragma unroll
    for (int i = 0; i < 9; i++) t[i] = __int_as_float(0x7f800000);
    for (int j = tid; j < MB_N; j += 1024) {
        float v = g_d2row[j];
        if (v < t[8]) {
            t[8] = v;
            #pragma unroll
            for (int i = 8; i > 0; i--) {
                float a = fminf(t[i - 1], t[i]);
                float b = fmaxf(t[i - 1], t[i]);
                t[i - 1] = a; t[i] = b;
            }
        }
    }
    #pragma unroll
    for (int i = 0; i < 9; i++) s[tid * 9 + i] = t[i];
    __syncthreads();

    for (int r = 0; r < 9; r++) {
        float lv = __int_as_float(0x7f800000);
        int   li = -1;
        #pragma unroll
        for (int i = 0; i < 9; i++) {
            float v = s[tid * 9 + i];
            if (v < lv) { lv = v; li = tid * 9 + i; }
        }
        rv[tid] = lv; ri[tid] = li;
        __syncthreads();
        for (int off = 512; off > 0; off >>= 1) {
            if (tid < off) {
                if (rv[tid + off] < rv[tid]) { rv[tid] = rv[tid + off]; ri[tid] = ri[tid + off]; }
            }
            __syncthreads();
        }
        if (tid == 0) {
            cf[r] = sqrtf(fmaxf(rv[0], 1e-12f));
            s[ri[0]] = __int_as_float(0x7f800000);
        }
        __syncthreads();
    }

    if (tid == 0) {
        double emax = exp((double)cf[8]);
        double sum = 0.0;
        #pragma unroll
        for (int i = 0; i < 9; i++) sum += exp((double)cf[i]);
        double weight = 1.0 - emax / sum;
        out[out_size - 1] = (float)(weight * (double)cf[0]);
    }
}

// ---------------- 7) bilinear resize 28 -> 224 ----------------
__global__ void __launch_bounds__(256) resize_kernel() {
    int o = blockIdx.x * 256 + threadIdx.x;
    if (o >= OUTPIX) return;
    int oy = o / OUTHW, ox = o % OUTHW;
    float fy = oy * 0.125f - 0.4375f;
    float fx = ox * 0.125f - 0.4375f;
    int y0 = (int)floorf(fy);
    int x0 = (int)floorf(fx);
    float wy = fy - (float)y0;
    float wx = fx - (float)x0;
    int y0c = min(max(y0, 0), 27), y1c = min(max(y0 + 1, 0), 27);
    int x0c = min(max(x0, 0), 27), x1c = min(max(x0 + 1, 0), 27);
    float v00 = g_amap28[y0c * 28 + x0c];
    float v01 = g_amap28[y0c * 28 + x1c];
    float v10 = g_amap28[y1c * 28 + x0c];
    float v11 = g_amap28[y1c * 28 + x1c];
    g_t0[o] = (1.f - wy) * ((1.f - wx) * v00 + wx * v01)
            + wy * ((1.f - wx) * v10 + wx * v11);
}

// ---------------- 8/9) separable gaussian ----------------
__device__ __forceinline__ int refl224(int i) {
    if (i < 0) return -1 - i;
    if (i > 223) return 447 - i;
    return i;
}

__global__ void __launch_bounds__(256) gaussv_kernel() {
    __shared__ float w[33];
    int tid = threadIdx.x;
    if (tid < 33) {
        float d = (float)tid - 16.f;
        w[tid] = expf(-d * d / 32.f);
    }
    __syncthreads();
    float Z = 0.f;
    #pragma unroll
    for (int i = 0; i < 33; i++) Z += w[i];
    float inv = 1.f / Z;
    int o = blockIdx.x * 256 + tid;
    if (o >= OUTPIX) return;
    int y = o / OUTHW, x = o % OUTHW;
    float s = 0.f;
    #pragma unroll
    for (int d = 0; d < 33; d++) {
        int yy = refl224(y + d - 16);
        s += w[d] * g_t0[yy * OUTHW + x];
    }
    g_t1[o] = s * inv;
}

__global__ void __launch_bounds__(256) gaussh_kernel(float* __restrict__ out) {
    __shared__ float w[33];
    int tid = threadIdx.x;
    if (tid < 33) {
        float d = (float)tid - 16.f;
        w[tid] = expf(-d * d / 32.f);
    }
    __syncthreads();
    float Z = 0.f;
    #pragma unroll
    for (int i = 0; i < 33; i++) Z += w[i];
    float inv = 1.f / Z;
    int o = blockIdx.x * 256 + tid;
    if (o >= OUTPIX) return;
    int y = o / OUTHW, x = o % OUTHW;
    float s = 0.f;
    #pragma unroll
    for (int d = 0; d < 33; d++) {
        int xx = refl224(x + d - 16);
        s += w[d] * g_t1[y * OUTHW + xx];
    }
    out[o] = s * inv;
}

// ---------------- launch ----------------
extern "C" void kernel_launch(void* const* d_in, const int* in_sizes, int n_in,
                              void* d_out, int out_size) {
    const float* f2   = (const float*)d_in[0];
    const float* f3   = (const float*)d_in[1];
    const float* bank = (const float*)d_in[2];
    float* out = (float*)d_out;

    cudaFuncSetAttribute(distmin_mma_kernel,
                         cudaFuncAttributeMaxDynamicSharedMemorySize, SMEM_REQ);

    embed_kernel<<<NPIX, 256>>>(f2, f3);
    convert_bank_kernel<<<1536, 256>>>(bank);

    dim3 g(7, MB_PAD / 128);   // x<6: full 128-row tiles; x==6: 16-row tail
    distmin_mma_kernel<<<g, 256, SMEM_REQ>>>();

    scores_kernel<<<1, 1024>>>();
    row_dist_kernel<<<1563, 256>>>();
    top9_kernel<<<1, 1024>>>(out, out_size);

    resize_kernel<<<(OUTPIX + 255) / 256, 256>>>();
    gaussv_kernel<<<(OUTPIX + 255) / 256, 256>>>();
    gaussh_kernel<<<(OUTPIX + 255) / 256, 256>>>(out);
}